// round 2
// baseline (speedup 1.0000x reference)
#include <cuda_runtime.h>

// ---------------- problem constants ----------------
#define TLEN  32768
#define BATCH 4
#define RC    120
#define RCP   128     // padded residual channels
#define SC    240
#define SCP   256     // padded skip / gate channels
#define NMEL  80
#define K1    336     // 128 (shift tap) + 128 (tap1) + 80 (cond)
#define NBLK  16
#define NCH   256
#define TT    64      // time tile per CTA

typedef unsigned long long ull;

// ---------------- device scratch (no allocations allowed) ----------------
__device__ float g_res0[BATCH * RCP * TLEN];
__device__ float g_res1[BATCH * RCP * TLEN];
__device__ float g_skip[BATCH * SCP * TLEN];
__device__ float g_obuf[BATCH * NCH * TLEN];

__device__ float g_Wg[NBLK * K1 * SCP];    // gate GEMM weights, k-major [i][k][o]
__device__ float g_Bg[NBLK * SCP];         // gate bias (dil_b + cond_b), padded
__device__ float g_W2[NBLK * RCP * 384];   // [i][k][ skip(256) | res(128) ]
__device__ float g_B2[NBLK * 384];         // [ skip_b(256 pad) | res_b(128 pad) ]
__device__ float g_Wo[256 * 256];          // out_w packed [k][o], k>=240 zero
__device__ float g_We[256 * 256];          // end_w packed [k][o]

// ---------------- f32x2 helpers ----------------
__device__ __forceinline__ ull pk2(float lo, float hi) {
    ull r;
    asm("mov.b64 %0, {%1,%2};" : "=l"(r) : "f"(lo), "f"(hi));
    return r;
}
__device__ __forceinline__ float2 upk2(ull v) {
    float2 r;
    asm("mov.b64 {%0,%1}, %2;" : "=f"(r.x), "=f"(r.y) : "l"(v));
    return r;
}
#define FMA2(acc, w, b) \
    asm("fma.rn.f32x2 %0, %1, %2, %0;" : "+l"(acc) : "l"(w), "l"(b))

__device__ __forceinline__ float sigf(float x) {
    return 1.f / (1.f + __expf(-x));
}

// ---------------- pack kernels ----------------
__global__ void pack_wg(const float* __restrict__ dil_w, const float* __restrict__ cond_w) {
    int idx = blockIdx.x * blockDim.x + threadIdx.x;
    if (idx >= NBLK * K1 * SCP) return;
    int op = idx % SCP;
    int k  = (idx / SCP) % K1;
    int i  = idx / (SCP * K1);
    float v = 0.f;
    int o = (op < 128) ? op : (120 + (op - 128));     // padded -> original gate channel
    bool ov = (op < 128) ? (op < 120) : (op < 248);
    if (ov) {
        if (k < 128) {
            if (k < 120) v = dil_w[((i * 240 + o) * 120 + k) * 2 + 0];
        } else if (k < 256) {
            int c = k - 128;
            if (c < 120) v = dil_w[((i * 240 + o) * 120 + c) * 2 + 1];
        } else {
            v = cond_w[(i * 240 + o) * 80 + (k - 256)];
        }
    }
    g_Wg[idx] = v;
}

__global__ void pack_bg(const float* __restrict__ dil_b, const float* __restrict__ cond_b) {
    int idx = blockIdx.x * blockDim.x + threadIdx.x;
    if (idx >= NBLK * SCP) return;
    int op = idx % SCP;
    int i  = idx / SCP;
    int o = (op < 128) ? op : (120 + (op - 128));
    bool ov = (op < 128) ? (op < 120) : (op < 248);
    g_Bg[idx] = ov ? (dil_b[i * 240 + o] + cond_b[i * 240 + o]) : 0.f;
}

__global__ void pack_w2(const float* __restrict__ skip_w, const float* __restrict__ res_w) {
    int idx = blockIdx.x * blockDim.x + threadIdx.x;
    if (idx >= NBLK * RCP * 384) return;
    int j = idx % 384;
    int k = (idx / 384) % RCP;
    int i = idx / (384 * RCP);
    float v = 0.f;
    if (k < 120) {
        if (j < 256) {
            if (j < 240) v = skip_w[(i * 240 + j) * 120 + k];
        } else {
            int o = j - 256;
            if (o < 120) v = res_w[(i * 120 + o) * 120 + k];
        }
    }
    g_W2[idx] = v;
}

__global__ void pack_b2(const float* __restrict__ skip_b, const float* __restrict__ res_b) {
    int idx = blockIdx.x * blockDim.x + threadIdx.x;
    if (idx >= NBLK * 384) return;
    int j = idx % 384;
    int i = idx / 384;
    float v = 0.f;
    if (j < 240) v = skip_b[i * 240 + j];
    else if (j >= 256 && j < 376) v = res_b[i * 120 + (j - 256)];
    g_B2[idx] = v;
}

__global__ void pack_wo(const float* __restrict__ out_w) {
    int idx = blockIdx.x * blockDim.x + threadIdx.x;
    if (idx >= 256 * 256) return;
    int o = idx % 256;
    int k = idx / 256;
    g_Wo[idx] = (k < 240) ? out_w[o * 240 + k] : 0.f;
}

__global__ void pack_we(const float* __restrict__ end_w) {
    int idx = blockIdx.x * blockDim.x + threadIdx.x;
    if (idx >= 256 * 256) return;
    int o = idx % 256;
    int k = idx / 256;
    g_We[idx] = end_w[o * 256 + k];
}

__global__ void init_res(const float* __restrict__ wav, const float* __restrict__ wav_w,
                         const float* __restrict__ wav_b) {
    int idx = blockIdx.x * blockDim.x + threadIdx.x;
    if (idx >= BATCH * RCP * TLEN) return;
    int t = idx % TLEN;
    int r = (idx / TLEN) % RCP;
    int b = idx / (TLEN * RCP);
    g_res0[idx] = (r < 120) ? (wav_w[r] * wav[b * TLEN + t] + wav_b[r]) : 0.f;
}

// ---------------- fused per-block kernel ----------------
// smem layout (floats): sShift[128*64] | sRes[128*64] | sCond[80*64] | sOut[128*64] | sW[16*384]
#define SMEM_BLK_FLOATS (8192 + 8192 + 5120 + 8192 + 6144)

__global__ __launch_bounds__(256, 1)
void block_kernel(int blk, int d, int src, int first, const float* __restrict__ cond) {
    extern __shared__ float sm[];
    float* sShift = sm;
    float* sRes   = sm + 8192;
    float* sCond  = sm + 16384;
    float* sOut   = sm + 21504;
    float* sW     = sm + 29696;

    const float* __restrict__ rin = src ? g_res1 : g_res0;
    float* __restrict__ rout      = src ? g_res0 : g_res1;

    int tid = threadIdx.x;
    int tx = tid & 31;       // time pair index: t = tx*2 + s
    int ty = tid >> 5;       // channel group 0..7
    int b  = blockIdx.y;
    int t0 = blockIdx.x * TT;

    // load sRes (current-time tap) via float4
    for (int q = tid; q < 2048; q += 256) {
        int r = q >> 4, c4 = q & 15;
        float4 v = *(const float4*)&rin[(b * RCP + r) * TLEN + t0 + c4 * 4];
        *(float4*)&sRes[r * 64 + c4 * 4] = v;
    }
    // load sShift (t-d tap), scalar w/ zero pad
    for (int q = tid; q < 8192; q += 256) {
        int r = q >> 6, tt = q & 63;
        int tg = t0 - d + tt;
        sShift[q] = (tg >= 0) ? rin[(b * RCP + r) * TLEN + tg] : 0.f;
    }
    // load sCond via float4
    for (int q = tid; q < 1280; q += 256) {
        int r = q >> 4, c4 = q & 15;
        float4 v = *(const float4*)&cond[(b * NMEL + r) * TLEN + t0 + c4 * 4];
        *(float4*)&sCond[r * 64 + c4 * 4] = v;
    }
    __syncthreads();

    // -------- stage 1: gate GEMM [256 x 64], K=336 --------
    ull aT[2][8], aS[2][8];
    {
        const ull* bg = (const ull*)(g_Bg + blk * SCP);
        #pragma unroll
        for (int j = 0; j < 8; j++) {
            ull bt = bg[ty * 8 + j];        // tanh channels o = ty*16+2j
            ull bs = bg[64 + ty * 8 + j];   // sigmoid channels (offset 128 floats)
            aT[0][j] = bt; aT[1][j] = bt;
            aS[0][j] = bs; aS[1][j] = bs;
        }
    }
    for (int kb = 0; kb < K1; kb += 16) {
        const float4* wsrc = (const float4*)(g_Wg + (blk * K1 + kb) * SCP);
        float4* wdst = (float4*)sW;
        #pragma unroll
        for (int q = 0; q < 4; q++) wdst[tid + q * 256] = wsrc[tid + q * 256];
        __syncthreads();
        const float* bs = (kb < 128) ? (sShift + kb * 64)
                        : (kb < 256) ? (sRes + (kb - 128) * 64)
                                     : (sCond + (kb - 256) * 64);
        #pragma unroll
        for (int r = 0; r < 16; r++) {
            float2 bv = *(const float2*)(bs + r * 64 + tx * 2);
            ull b0 = pk2(bv.x, bv.x), b1 = pk2(bv.y, bv.y);
            const ulonglong2* wt = (const ulonglong2*)(sW + r * 256 + ty * 16);
            const ulonglong2* ws = (const ulonglong2*)(sW + r * 256 + 128 + ty * 16);
            #pragma unroll
            for (int q = 0; q < 4; q++) {
                ulonglong2 w = wt[q];
                FMA2(aT[0][2 * q],     w.x, b0); FMA2(aT[1][2 * q],     w.x, b1);
                FMA2(aT[0][2 * q + 1], w.y, b0); FMA2(aT[1][2 * q + 1], w.y, b1);
                ulonglong2 v = ws[q];
                FMA2(aS[0][2 * q],     v.x, b0); FMA2(aS[1][2 * q],     v.x, b1);
                FMA2(aS[0][2 * q + 1], v.y, b0); FMA2(aS[1][2 * q + 1], v.y, b1);
            }
        }
        __syncthreads();
    }

    // gating -> sOut[128][64]
    #pragma unroll
    for (int s = 0; s < 2; s++) {
        int t = tx * 2 + s;
        #pragma unroll
        for (int j = 0; j < 8; j++) {
            float2 a = upk2(aT[s][j]);
            float2 g = upk2(aS[s][j]);
            int o = ty * 16 + 2 * j;
            sOut[o * 64 + t]       = tanhf(a.x) * sigf(g.x);
            sOut[(o + 1) * 64 + t] = tanhf(a.y) * sigf(g.y);
        }
    }
    __syncthreads();

    // -------- stage 2: skip (256) + res (128) GEMMs, K=128 --------
    ull ak[2][16], ar[2][8];
    {
        const ull* b2 = (const ull*)(g_B2 + blk * 384);
        #pragma unroll
        for (int j = 0; j < 16; j++) { ull v = b2[ty * 16 + j]; ak[0][j] = v; ak[1][j] = v; }
        #pragma unroll
        for (int j = 0; j < 8; j++)  { ull v = b2[128 + ty * 8 + j]; ar[0][j] = v; ar[1][j] = v; }
    }
    for (int kb = 0; kb < 128; kb += 16) {
        const float4* wsrc = (const float4*)(g_W2 + (blk * RCP + kb) * 384);
        float4* wdst = (float4*)sW;
        #pragma unroll
        for (int q = 0; q < 6; q++) wdst[tid + q * 256] = wsrc[tid + q * 256];
        __syncthreads();
        #pragma unroll
        for (int r = 0; r < 16; r++) {
            float2 bv = *(const float2*)(sOut + (kb + r) * 64 + tx * 2);
            ull b0 = pk2(bv.x, bv.x), b1 = pk2(bv.y, bv.y);
            const ulonglong2* wk = (const ulonglong2*)(sW + r * 384 + ty * 32);
            #pragma unroll
            for (int q = 0; q < 8; q++) {
                ulonglong2 w = wk[q];
                FMA2(ak[0][2 * q],     w.x, b0); FMA2(ak[1][2 * q],     w.x, b1);
                FMA2(ak[0][2 * q + 1], w.y, b0); FMA2(ak[1][2 * q + 1], w.y, b1);
            }
            const ulonglong2* wr = (const ulonglong2*)(sW + r * 384 + 256 + ty * 16);
            #pragma unroll
            for (int q = 0; q < 4; q++) {
                ulonglong2 w = wr[q];
                FMA2(ar[0][2 * q],     w.x, b0); FMA2(ar[1][2 * q],     w.x, b1);
                FMA2(ar[0][2 * q + 1], w.y, b0); FMA2(ar[1][2 * q + 1], w.y, b1);
            }
        }
        __syncthreads();
    }

    // epilogue: skip accumulate + residual write
    float* skp = g_skip + (b * SCP) * TLEN + t0;
    #pragma unroll
    for (int s = 0; s < 2; s++) {
        int t = tx * 2 + s;
        #pragma unroll
        for (int j = 0; j < 16; j++) {
            int o = ty * 32 + 2 * j;
            float2 v = upk2(ak[s][j]);
            if (!first) {
                v.x += skp[o * TLEN + t];
                v.y += skp[(o + 1) * TLEN + t];
            }
            skp[o * TLEN + t]       = v.x;
            skp[(o + 1) * TLEN + t] = v.y;
        }
    }
    float* rp = rout + (b * RCP) * TLEN + t0;
    #pragma unroll
    for (int s = 0; s < 2; s++) {
        int t = tx * 2 + s;
        #pragma unroll
        for (int j = 0; j < 8; j++) {
            int o = ty * 16 + 2 * j;
            float2 v = upk2(ar[s][j]);
            v.x += sRes[o * 64 + t];
            v.y += sRes[(o + 1) * 64 + t];
            rp[o * TLEN + t]       = v.x;
            rp[(o + 1) * TLEN + t] = v.y;
        }
    }
}

// ---------------- out / end GEMM (O=256, K=256, relu on input) ----------------
#define SMEM_G_FLOATS (16384 + 4096)

__global__ __launch_bounds__(256, 1)
void gemm256_kernel(int which, const float* __restrict__ bias, float* __restrict__ out_ext) {
    extern __shared__ float sm[];
    float* sIn = sm;            // 256*64
    float* sW  = sm + 16384;    // 16*256

    const float* __restrict__ in = which ? g_obuf : g_skip;
    const float* __restrict__ W  = which ? g_We   : g_Wo;
    float* __restrict__ dst      = which ? out_ext : g_obuf;

    int tid = threadIdx.x;
    int tx = tid & 31, ty = tid >> 5;
    int b = blockIdx.y, t0 = blockIdx.x * TT;

    for (int q = tid; q < 4096; q += 256) {
        int r = q >> 4, c4 = q & 15;
        float4 v = *(const float4*)&in[(b * 256 + r) * TLEN + t0 + c4 * 4];
        v.x = fmaxf(v.x, 0.f); v.y = fmaxf(v.y, 0.f);
        v.z = fmaxf(v.z, 0.f); v.w = fmaxf(v.w, 0.f);
        *(float4*)&sIn[r * 64 + c4 * 4] = v;
    }
    __syncthreads();

    ull a[2][16];
    {
        const ull* bb = (const ull*)bias;
        #pragma unroll
        for (int j = 0; j < 16; j++) { ull v = bb[ty * 16 + j]; a[0][j] = v; a[1][j] = v; }
    }
    for (int kb = 0; kb < 256; kb += 16) {
        const float4* wsrc = (const float4*)(W + kb * 256);
        float4* wdst = (float4*)sW;
        #pragma unroll
        for (int q = 0; q < 4; q++) wdst[tid + q * 256] = wsrc[tid + q * 256];
        __syncthreads();
        #pragma unroll
        for (int r = 0; r < 16; r++) {
            float2 bv = *(const float2*)(sIn + (kb + r) * 64 + tx * 2);
            ull b0 = pk2(bv.x, bv.x), b1 = pk2(bv.y, bv.y);
            const ulonglong2* wk = (const ulonglong2*)(sW + r * 256 + ty * 32);
            #pragma unroll
            for (int q = 0; q < 8; q++) {
                ulonglong2 w = wk[q];
                FMA2(a[0][2 * q],     w.x, b0); FMA2(a[1][2 * q],     w.x, b1);
                FMA2(a[0][2 * q + 1], w.y, b0); FMA2(a[1][2 * q + 1], w.y, b1);
            }
        }
        __syncthreads();
    }

    #pragma unroll
    for (int s = 0; s < 2; s++) {
        int t = tx * 2 + s;
        #pragma unroll
        for (int j = 0; j < 16; j++) {
            int o = ty * 32 + 2 * j;
            float2 v = upk2(a[s][j]);
            dst[(b * 256 + o) * TLEN + t0 + t]       = v.x;
            dst[(b * 256 + o + 1) * TLEN + t0 + t]   = v.y;
        }
    }
}

// ---------------- launch ----------------
extern "C" void kernel_launch(void* const* d_in, const int* in_sizes, int n_in,
                              void* d_out, int out_size) {
    const float* wav    = (const float*)d_in[0];
    const float* cond   = (const float*)d_in[1];
    const float* wav_w  = (const float*)d_in[2];
    const float* wav_b  = (const float*)d_in[3];
    const float* cond_w = (const float*)d_in[4];
    const float* cond_b = (const float*)d_in[5];
    const float* dil_w  = (const float*)d_in[6];
    const float* dil_b  = (const float*)d_in[7];
    const float* skip_w = (const float*)d_in[8];
    const float* skip_b = (const float*)d_in[9];
    const float* res_w  = (const float*)d_in[10];
    const float* res_b  = (const float*)d_in[11];
    const float* out_w  = (const float*)d_in[12];
    const float* out_b  = (const float*)d_in[13];
    const float* end_w  = (const float*)d_in[14];
    const float* end_b  = (const float*)d_in[15];

    const int smem_blk = SMEM_BLK_FLOATS * 4;
    const int smem_g   = SMEM_G_FLOATS * 4;
    cudaFuncSetAttribute(block_kernel, cudaFuncAttributeMaxDynamicSharedMemorySize, smem_blk);
    cudaFuncSetAttribute(gemm256_kernel, cudaFuncAttributeMaxDynamicSharedMemorySize, smem_g);

    // pack weights
    pack_wg<<<(NBLK * K1 * SCP + 255) / 256, 256>>>(dil_w, cond_w);
    pack_bg<<<(NBLK * SCP + 255) / 256, 256>>>(dil_b, cond_b);
    pack_w2<<<(NBLK * RCP * 384 + 255) / 256, 256>>>(skip_w, res_w);
    pack_b2<<<(NBLK * 384 + 255) / 256, 256>>>(skip_b, res_b);
    pack_wo<<<(256 * 256 + 255) / 256, 256>>>(out_w);
    pack_we<<<(256 * 256 + 255) / 256, 256>>>(end_w);
    init_res<<<(BATCH * RCP * TLEN + 255) / 256, 256>>>(wav, wav_w, wav_b);

    dim3 grid(TLEN / TT, BATCH);
    for (int i = 0; i < NBLK; i++) {
        block_kernel<<<grid, 256, smem_blk>>>(i, 1 << (i % 8), i & 1, (i == 0) ? 1 : 0, cond);
    }
    gemm256_kernel<<<grid, 256, smem_g>>>(0, out_b, nullptr);
    gemm256_kernel<<<grid, 256, smem_g>>>(1, end_b, (float*)d_out);
}

// round 3
// speedup vs baseline: 1.0003x; 1.0003x over previous
#include <cuda_runtime.h>

// ---------------- problem constants ----------------
#define TLEN  32768
#define BATCH 4
#define RC    120
#define RCP   128     // padded residual channels
#define SC    240
#define SCP   256     // padded skip / gate channels
#define NMEL  80
#define K1    336     // 128 (shift tap) + 128 (tap1) + 80 (cond)
#define NBLK  16
#define NCH   256
#define TT    64      // time tile per CTA

typedef unsigned long long ull;

// ---------------- device scratch (no allocations allowed) ----------------
__device__ float g_res0[BATCH * RCP * TLEN];
__device__ float g_res1[BATCH * RCP * TLEN];
__device__ float g_skip[BATCH * SCP * TLEN];
__device__ float g_obuf[BATCH * NCH * TLEN];

__device__ float g_Wg[NBLK * K1 * SCP];    // gate GEMM weights, k-major [i][k][o]
__device__ float g_Bg[NBLK * SCP];         // gate bias (dil_b + cond_b), padded
__device__ float g_W2[NBLK * RCP * 384];   // [i][k][ skip(256) | res(128) ]
__device__ float g_B2[NBLK * 384];         // [ skip_b(256 pad) | res_b(128 pad) ]
__device__ float g_Wo[256 * 256];          // out_w packed [k][o], k>=240 zero
__device__ float g_We[256 * 256];          // end_w packed [k][o]

// ---------------- f32x2 helpers ----------------
__device__ __forceinline__ ull pk2(float lo, float hi) {
    ull r;
    asm("mov.b64 %0, {%1,%2};" : "=l"(r) : "f"(lo), "f"(hi));
    return r;
}
__device__ __forceinline__ float2 upk2(ull v) {
    float2 r;
    asm("mov.b64 {%0,%1}, %2;" : "=f"(r.x), "=f"(r.y) : "l"(v));
    return r;
}
#define FMA2(acc, w, b) \
    asm("fma.rn.f32x2 %0, %1, %2, %0;" : "+l"(acc) : "l"(w), "l"(b))

__device__ __forceinline__ float sigf(float x) {
    return 1.f / (1.f + __expf(-x));
}

// ---------------- pack kernels ----------------
__global__ void pack_wg(const float* __restrict__ dil_w, const float* __restrict__ cond_w) {
    int idx = blockIdx.x * blockDim.x + threadIdx.x;
    if (idx >= NBLK * K1 * SCP) return;
    int op = idx % SCP;
    int k  = (idx / SCP) % K1;
    int i  = idx / (SCP * K1);
    float v = 0.f;
    int o = (op < 128) ? op : (120 + (op - 128));     // padded -> original gate channel
    bool ov = (op < 128) ? (op < 120) : (op < 248);
    if (ov) {
        if (k < 128) {
            if (k < 120) v = dil_w[((i * 240 + o) * 120 + k) * 2 + 0];
        } else if (k < 256) {
            int c = k - 128;
            if (c < 120) v = dil_w[((i * 240 + o) * 120 + c) * 2 + 1];
        } else {
            v = cond_w[(i * 240 + o) * 80 + (k - 256)];
        }
    }
    g_Wg[idx] = v;
}

__global__ void pack_bg(const float* __restrict__ dil_b, const float* __restrict__ cond_b) {
    int idx = blockIdx.x * blockDim.x + threadIdx.x;
    if (idx >= NBLK * SCP) return;
    int op = idx % SCP;
    int i  = idx / SCP;
    int o = (op < 128) ? op : (120 + (op - 128));
    bool ov = (op < 128) ? (op < 120) : (op < 248);
    g_Bg[idx] = ov ? (dil_b[i * 240 + o] + cond_b[i * 240 + o]) : 0.f;
}

__global__ void pack_w2(const float* __restrict__ skip_w, const float* __restrict__ res_w) {
    int idx = blockIdx.x * blockDim.x + threadIdx.x;
    if (idx >= NBLK * RCP * 384) return;
    int j = idx % 384;
    int k = (idx / 384) % RCP;
    int i = idx / (384 * RCP);
    float v = 0.f;
    if (k < 120) {
        if (j < 256) {
            if (j < 240) v = skip_w[(i * 240 + j) * 120 + k];
        } else {
            int o = j - 256;
            if (o < 120) v = res_w[(i * 120 + o) * 120 + k];
        }
    }
    g_W2[idx] = v;
}

__global__ void pack_b2(const float* __restrict__ skip_b, const float* __restrict__ res_b) {
    int idx = blockIdx.x * blockDim.x + threadIdx.x;
    if (idx >= NBLK * 384) return;
    int j = idx % 384;
    int i = idx / 384;
    float v = 0.f;
    if (j < 240) v = skip_b[i * 240 + j];
    else if (j >= 256 && j < 376) v = res_b[i * 120 + (j - 256)];
    g_B2[idx] = v;
}

__global__ void pack_wo(const float* __restrict__ out_w) {
    int idx = blockIdx.x * blockDim.x + threadIdx.x;
    if (idx >= 256 * 256) return;
    int o = idx % 256;
    int k = idx / 256;
    g_Wo[idx] = (k < 240) ? out_w[o * 240 + k] : 0.f;
}

__global__ void pack_we(const float* __restrict__ end_w) {
    int idx = blockIdx.x * blockDim.x + threadIdx.x;
    if (idx >= 256 * 256) return;
    int o = idx % 256;
    int k = idx / 256;
    g_We[idx] = end_w[o * 256 + k];
}

__global__ void init_res(const float* __restrict__ wav, const float* __restrict__ wav_w,
                         const float* __restrict__ wav_b) {
    int idx = blockIdx.x * blockDim.x + threadIdx.x;
    if (idx >= BATCH * RCP * TLEN) return;
    int t = idx % TLEN;
    int r = (idx / TLEN) % RCP;
    int b = idx / (TLEN * RCP);
    g_res0[idx] = (r < 120) ? (wav_w[r] * wav[b * TLEN + t] + wav_b[r]) : 0.f;
}

// ---------------- fused per-block kernel ----------------
// smem layout (floats): sShift[128*64] | sRes[128*64] | sCond[80*64] | sOut[128*64] | sW[16*384]
#define SMEM_BLK_FLOATS (8192 + 8192 + 5120 + 8192 + 6144)

__global__ __launch_bounds__(256, 1)
void block_kernel(int blk, int d, int src, int first, const float* __restrict__ cond) {
    extern __shared__ float sm[];
    float* sShift = sm;
    float* sRes   = sm + 8192;
    float* sCond  = sm + 16384;
    float* sOut   = sm + 21504;
    float* sW     = sm + 29696;

    const float* __restrict__ rin = src ? g_res1 : g_res0;
    float* __restrict__ rout      = src ? g_res0 : g_res1;

    int tid = threadIdx.x;
    int tx = tid & 31;       // time pair index: t = tx*2 + s
    int ty = tid >> 5;       // channel group 0..7
    int b  = blockIdx.y;
    int t0 = blockIdx.x * TT;

    // load sRes (current-time tap) via float4
    for (int q = tid; q < 2048; q += 256) {
        int r = q >> 4, c4 = q & 15;
        float4 v = *(const float4*)&rin[(b * RCP + r) * TLEN + t0 + c4 * 4];
        *(float4*)&sRes[r * 64 + c4 * 4] = v;
    }
    // load sShift (t-d tap), scalar w/ zero pad
    for (int q = tid; q < 8192; q += 256) {
        int r = q >> 6, tt = q & 63;
        int tg = t0 - d + tt;
        sShift[q] = (tg >= 0) ? rin[(b * RCP + r) * TLEN + tg] : 0.f;
    }
    // load sCond via float4
    for (int q = tid; q < 1280; q += 256) {
        int r = q >> 4, c4 = q & 15;
        float4 v = *(const float4*)&cond[(b * NMEL + r) * TLEN + t0 + c4 * 4];
        *(float4*)&sCond[r * 64 + c4 * 4] = v;
    }
    __syncthreads();

    // -------- stage 1: gate GEMM [256 x 64], K=336 --------
    ull aT[2][8], aS[2][8];
    {
        const ull* bg = (const ull*)(g_Bg + blk * SCP);
        #pragma unroll
        for (int j = 0; j < 8; j++) {
            ull bt = bg[ty * 8 + j];        // tanh channels o = ty*16+2j
            ull bs = bg[64 + ty * 8 + j];   // sigmoid channels (offset 128 floats)
            aT[0][j] = bt; aT[1][j] = bt;
            aS[0][j] = bs; aS[1][j] = bs;
        }
    }
    for (int kb = 0; kb < K1; kb += 16) {
        const float4* wsrc = (const float4*)(g_Wg + (blk * K1 + kb) * SCP);
        float4* wdst = (float4*)sW;
        #pragma unroll
        for (int q = 0; q < 4; q++) wdst[tid + q * 256] = wsrc[tid + q * 256];
        __syncthreads();
        const float* bs = (kb < 128) ? (sShift + kb * 64)
                        : (kb < 256) ? (sRes + (kb - 128) * 64)
                                     : (sCond + (kb - 256) * 64);
        #pragma unroll
        for (int r = 0; r < 16; r++) {
            float2 bv = *(const float2*)(bs + r * 64 + tx * 2);
            ull b0 = pk2(bv.x, bv.x), b1 = pk2(bv.y, bv.y);
            const ulonglong2* wt = (const ulonglong2*)(sW + r * 256 + ty * 16);
            const ulonglong2* ws = (const ulonglong2*)(sW + r * 256 + 128 + ty * 16);
            #pragma unroll
            for (int q = 0; q < 4; q++) {
                ulonglong2 w = wt[q];
                FMA2(aT[0][2 * q],     w.x, b0); FMA2(aT[1][2 * q],     w.x, b1);
                FMA2(aT[0][2 * q + 1], w.y, b0); FMA2(aT[1][2 * q + 1], w.y, b1);
                ulonglong2 v = ws[q];
                FMA2(aS[0][2 * q],     v.x, b0); FMA2(aS[1][2 * q],     v.x, b1);
                FMA2(aS[0][2 * q + 1], v.y, b0); FMA2(aS[1][2 * q + 1], v.y, b1);
            }
        }
        __syncthreads();
    }

    // gating -> sOut[128][64]
    #pragma unroll
    for (int s = 0; s < 2; s++) {
        int t = tx * 2 + s;
        #pragma unroll
        for (int j = 0; j < 8; j++) {
            float2 a = upk2(aT[s][j]);
            float2 g = upk2(aS[s][j]);
            int o = ty * 16 + 2 * j;
            sOut[o * 64 + t]       = tanhf(a.x) * sigf(g.x);
            sOut[(o + 1) * 64 + t] = tanhf(a.y) * sigf(g.y);
        }
    }
    __syncthreads();

    // -------- stage 2: skip (256) + res (128) GEMMs, K=128 --------
    ull ak[2][16], ar[2][8];
    {
        const ull* b2 = (const ull*)(g_B2 + blk * 384);
        #pragma unroll
        for (int j = 0; j < 16; j++) { ull v = b2[ty * 16 + j]; ak[0][j] = v; ak[1][j] = v; }
        #pragma unroll
        for (int j = 0; j < 8; j++)  { ull v = b2[128 + ty * 8 + j]; ar[0][j] = v; ar[1][j] = v; }
    }
    for (int kb = 0; kb < 128; kb += 16) {
        const float4* wsrc = (const float4*)(g_W2 + (blk * RCP + kb) * 384);
        float4* wdst = (float4*)sW;
        #pragma unroll
        for (int q = 0; q < 6; q++) wdst[tid + q * 256] = wsrc[tid + q * 256];
        __syncthreads();
        #pragma unroll
        for (int r = 0; r < 16; r++) {
            float2 bv = *(const float2*)(sOut + (kb + r) * 64 + tx * 2);
            ull b0 = pk2(bv.x, bv.x), b1 = pk2(bv.y, bv.y);
            const ulonglong2* wk = (const ulonglong2*)(sW + r * 384 + ty * 32);
            #pragma unroll
            for (int q = 0; q < 8; q++) {
                ulonglong2 w = wk[q];
                FMA2(ak[0][2 * q],     w.x, b0); FMA2(ak[1][2 * q],     w.x, b1);
                FMA2(ak[0][2 * q + 1], w.y, b0); FMA2(ak[1][2 * q + 1], w.y, b1);
            }
            const ulonglong2* wr = (const ulonglong2*)(sW + r * 384 + 256 + ty * 16);
            #pragma unroll
            for (int q = 0; q < 4; q++) {
                ulonglong2 w = wr[q];
                FMA2(ar[0][2 * q],     w.x, b0); FMA2(ar[1][2 * q],     w.x, b1);
                FMA2(ar[0][2 * q + 1], w.y, b0); FMA2(ar[1][2 * q + 1], w.y, b1);
            }
        }
        __syncthreads();
    }

    // epilogue: skip accumulate + residual write
    float* skp = g_skip + (b * SCP) * TLEN + t0;
    #pragma unroll
    for (int s = 0; s < 2; s++) {
        int t = tx * 2 + s;
        #pragma unroll
        for (int j = 0; j < 16; j++) {
            int o = ty * 32 + 2 * j;
            float2 v = upk2(ak[s][j]);
            if (!first) {
                v.x += skp[o * TLEN + t];
                v.y += skp[(o + 1) * TLEN + t];
            }
            skp[o * TLEN + t]       = v.x;
            skp[(o + 1) * TLEN + t] = v.y;
        }
    }
    float* rp = rout + (b * RCP) * TLEN + t0;
    #pragma unroll
    for (int s = 0; s < 2; s++) {
        int t = tx * 2 + s;
        #pragma unroll
        for (int j = 0; j < 8; j++) {
            int o = ty * 16 + 2 * j;
            float2 v = upk2(ar[s][j]);
            v.x += sRes[o * 64 + t];
            v.y += sRes[(o + 1) * 64 + t];
            rp[o * TLEN + t]       = v.x;
            rp[(o + 1) * TLEN + t] = v.y;
        }
    }
}

// ---------------- out / end GEMM (O=256, K=256, relu on input) ----------------
#define SMEM_G_FLOATS (16384 + 4096)

__global__ __launch_bounds__(256, 1)
void gemm256_kernel(int which, const float* __restrict__ bias, float* __restrict__ out_ext) {
    extern __shared__ float sm[];
    float* sIn = sm;            // 256*64
    float* sW  = sm + 16384;    // 16*256

    const float* __restrict__ in = which ? g_obuf : g_skip;
    const float* __restrict__ W  = which ? g_We   : g_Wo;
    float* __restrict__ dst      = which ? out_ext : g_obuf;

    int tid = threadIdx.x;
    int tx = tid & 31, ty = tid >> 5;
    int b = blockIdx.y, t0 = blockIdx.x * TT;

    for (int q = tid; q < 4096; q += 256) {
        int r = q >> 4, c4 = q & 15;
        float4 v = *(const float4*)&in[(b * 256 + r) * TLEN + t0 + c4 * 4];
        v.x = fmaxf(v.x, 0.f); v.y = fmaxf(v.y, 0.f);
        v.z = fmaxf(v.z, 0.f); v.w = fmaxf(v.w, 0.f);
        *(float4*)&sIn[r * 64 + c4 * 4] = v;
    }
    __syncthreads();

    ull a[2][16];
    {
        const ull* bb = (const ull*)bias;
        #pragma unroll
        for (int j = 0; j < 16; j++) { ull v = bb[ty * 16 + j]; a[0][j] = v; a[1][j] = v; }
    }
    for (int kb = 0; kb < 256; kb += 16) {
        const float4* wsrc = (const float4*)(W + kb * 256);
        float4* wdst = (float4*)sW;
        #pragma unroll
        for (int q = 0; q < 4; q++) wdst[tid + q * 256] = wsrc[tid + q * 256];
        __syncthreads();
        #pragma unroll
        for (int r = 0; r < 16; r++) {
            float2 bv = *(const float2*)(sIn + (kb + r) * 64 + tx * 2);
            ull b0 = pk2(bv.x, bv.x), b1 = pk2(bv.y, bv.y);
            const ulonglong2* wk = (const ulonglong2*)(sW + r * 256 + ty * 32);
            #pragma unroll
            for (int q = 0; q < 8; q++) {
                ulonglong2 w = wk[q];
                FMA2(a[0][2 * q],     w.x, b0); FMA2(a[1][2 * q],     w.x, b1);
                FMA2(a[0][2 * q + 1], w.y, b0); FMA2(a[1][2 * q + 1], w.y, b1);
            }
        }
        __syncthreads();
    }

    #pragma unroll
    for (int s = 0; s < 2; s++) {
        int t = tx * 2 + s;
        #pragma unroll
        for (int j = 0; j < 16; j++) {
            int o = ty * 32 + 2 * j;
            float2 v = upk2(a[s][j]);
            dst[(b * 256 + o) * TLEN + t0 + t]       = v.x;
            dst[(b * 256 + o + 1) * TLEN + t0 + t]   = v.y;
        }
    }
}

// ---------------- launch ----------------
extern "C" void kernel_launch(void* const* d_in, const int* in_sizes, int n_in,
                              void* d_out, int out_size) {
    const float* wav    = (const float*)d_in[0];
    const float* cond   = (const float*)d_in[1];
    const float* wav_w  = (const float*)d_in[2];
    const float* wav_b  = (const float*)d_in[3];
    const float* cond_w = (const float*)d_in[4];
    const float* cond_b = (const float*)d_in[5];
    const float* dil_w  = (const float*)d_in[6];
    const float* dil_b  = (const float*)d_in[7];
    const float* skip_w = (const float*)d_in[8];
    const float* skip_b = (const float*)d_in[9];
    const float* res_w  = (const float*)d_in[10];
    const float* res_b  = (const float*)d_in[11];
    const float* out_w  = (const float*)d_in[12];
    const float* out_b  = (const float*)d_in[13];
    const float* end_w  = (const float*)d_in[14];
    const float* end_b  = (const float*)d_in[15];

    const int smem_blk = SMEM_BLK_FLOATS * 4;
    const int smem_g   = SMEM_G_FLOATS * 4;
    cudaFuncSetAttribute(block_kernel, cudaFuncAttributeMaxDynamicSharedMemorySize, smem_blk);
    cudaFuncSetAttribute(gemm256_kernel, cudaFuncAttributeMaxDynamicSharedMemorySize, smem_g);

    // pack weights
    pack_wg<<<(NBLK * K1 * SCP + 255) / 256, 256>>>(dil_w, cond_w);
    pack_bg<<<(NBLK * SCP + 255) / 256, 256>>>(dil_b, cond_b);
    pack_w2<<<(NBLK * RCP * 384 + 255) / 256, 256>>>(skip_w, res_w);
    pack_b2<<<(NBLK * 384 + 255) / 256, 256>>>(skip_b, res_b);
    pack_wo<<<(256 * 256 + 255) / 256, 256>>>(out_w);
    pack_we<<<(256 * 256 + 255) / 256, 256>>>(end_w);
    init_res<<<(BATCH * RCP * TLEN + 255) / 256, 256>>>(wav, wav_w, wav_b);

    dim3 grid(TLEN / TT, BATCH);
    for (int i = 0; i < NBLK; i++) {
        block_kernel<<<grid, 256, smem_blk>>>(i, 1 << (i % 8), i & 1, (i == 0) ? 1 : 0, cond);
    }
    gemm256_kernel<<<grid, 256, smem_g>>>(0, out_b, nullptr);
    gemm256_kernel<<<grid, 256, smem_g>>>(1, end_b, (float*)d_out);
}

// round 6
// speedup vs baseline: 1.8723x; 1.8718x over previous
#include <cuda_runtime.h>
#include <cuda_bf16.h>
#include <cstdint>

#define TLEN 32768
#define BATCH 4
#define NMEL 80
#define NBLK 16
#define TN 128

#define SLOT_BYTES 58368
#define OFF_X_IN_SLOT 40960
#define X_HSTRIDE 8704
#define W_HSTRIDE 20480
#define OFF_XG 116736
#define XG_HSTRIDE 34816
#define SMEM_BLK 186368
#define SMEM_FIN 116736

typedef __nv_bfloat16 bf16;

// ---------------- device scratch ----------------
__device__ float g_res0[(size_t)BATCH*128*TLEN];
__device__ float g_res1[(size_t)BATCH*128*TLEN];
__device__ float g_skip[(size_t)BATCH*256*TLEN];
__device__ float g_obuf[(size_t)BATCH*256*TLEN];

// weights: bf16 hi/lo, chunked [.. chunk ..][h][rows][40]
__device__ bf16 g_Ws1[(size_t)NBLK*11*2*256*40];
__device__ bf16 g_Ws2[(size_t)NBLK*4*2*384*40];
__device__ bf16 g_Wf [(size_t)2*8*2*256*40];
__device__ float g_Bg2[NBLK*2*128];
__device__ float g_Bs[NBLK*256];
__device__ float g_Br[NBLK*128];

// ---------------- mma/ldmatrix helpers ----------------
__device__ __forceinline__ uint32_t smem_u32(const void* p) {
    uint32_t a;
    asm("{ .reg .u64 t; cvta.to.shared.u64 t, %1; cvt.u32.u64 %0, t; }" : "=r"(a) : "l"(p));
    return a;
}
__device__ __forceinline__ void mma16816(float* d, const uint32_t* a, const uint32_t* b) {
    asm volatile("mma.sync.aligned.m16n8k16.row.col.f32.bf16.bf16.f32 "
        "{%0,%1,%2,%3}, {%4,%5,%6,%7}, {%8,%9}, {%0,%1,%2,%3};"
        : "+f"(d[0]), "+f"(d[1]), "+f"(d[2]), "+f"(d[3])
        : "r"(a[0]), "r"(a[1]), "r"(a[2]), "r"(a[3]), "r"(b[0]), "r"(b[1]));
}
__device__ __forceinline__ void ldsm4(uint32_t* r, uint32_t addr) {
    asm volatile("ldmatrix.sync.aligned.m8n8.x4.shared.b16 {%0,%1,%2,%3}, [%4];"
        : "=r"(r[0]), "=r"(r[1]), "=r"(r[2]), "=r"(r[3]) : "r"(addr));
}
__device__ __forceinline__ void ldsm4t(uint32_t* r, uint32_t addr) {
    asm volatile("ldmatrix.sync.aligned.m8n8.x4.trans.shared.b16 {%0,%1,%2,%3}, [%4];"
        : "=r"(r[0]), "=r"(r[1]), "=r"(r[2]), "=r"(r[3]) : "r"(addr));
}

// one 32-logical-k chunk of triple-product (hi/lo) warp GEMM.
// W smem: [rows][40] bf16 at uWh / uWl.  X smem: [32k][136] bf16 at uXh / uXl.
template<int MT>
__device__ __forceinline__ void mma_chunk(float (*acc)[8][4],
    uint32_t uWh, uint32_t uWl, uint32_t uXh, uint32_t uXl,
    int rbase, int cbase, int lane)
{
    int lt = lane >> 3, lr = lane & 7;
    #pragma unroll
    for (int ks = 0; ks < 2; ks++) {
        uint32_t aH[MT][4], aL[MT][4];
        #pragma unroll
        for (int mt = 0; mt < MT; mt++) {
            uint32_t off = ((uint32_t)(rbase + mt*16 + (lt & 1)*8 + lr) * 40
                            + ks*16 + (lt >> 1)*8) * 2;
            ldsm4(aH[mt], uWh + off);
            ldsm4(aL[mt], uWl + off);
        }
        uint32_t krow = ks*16 + (lt & 1)*8 + lr;
        #pragma unroll
        for (int np = 0; np < 4; np++) {
            uint32_t boff = (krow*136 + (uint32_t)(cbase + np*16 + (lt >> 1)*8)) * 2;
            uint32_t bH[4], bL[4];
            ldsm4t(bH, uXh + boff);
            ldsm4t(bL, uXl + boff);
            #pragma unroll
            for (int mt = 0; mt < MT; mt++) {
                #pragma unroll
                for (int nh = 0; nh < 2; nh++) {
                    mma16816(acc[mt][np*2+nh], aH[mt], &bH[nh*2]);
                    mma16816(acc[mt][np*2+nh], aL[mt], &bH[nh*2]);
                    mma16816(acc[mt][np*2+nh], aH[mt], &bL[nh*2]);
                }
            }
        }
    }
}

// ---------------- pack kernels ----------------
__global__ void pack_s1(const float* __restrict__ dil_w, const float* __restrict__ cond_w) {
    size_t idx = (size_t)blockIdx.x * 256 + threadIdx.x;
    if (idx >= (size_t)NBLK*11*2*256*40) return;
    int kk = idx % 40;
    int m  = (idx / 40) % 256;
    int h  = (idx / (40*256)) % 2;
    int c  = (idx / (40*256*2)) % 11;
    int i  = idx / (40*256*2*11);
    float w = 0.f;
    if (kk < 32) {
        int k = c*32 + kk;
        int o = (m < 128) ? m : (120 + (m - 128));
        bool ov = (m < 128) ? (m < 120) : (m - 128 < 120);
        if (ov) {
            if (k < 128)      { if (k < 120) w = dil_w[((i*240+o)*120 + k)*2 + 0]; }
            else if (k < 256) { int q = k - 128; if (q < 120) w = dil_w[((i*240+o)*120 + q)*2 + 1]; }
            else if (k < 336) { int q = k - 256; if (q < NMEL) w = cond_w[(i*240+o)*80 + q]; }
        }
    }
    bf16 hi = __float2bfloat16_rn(w);
    g_Ws1[idx] = h ? __float2bfloat16_rn(w - __bfloat162float(hi)) : hi;
}
__global__ void pack_s2(const float* __restrict__ skip_w, const float* __restrict__ res_w) {
    size_t idx = (size_t)blockIdx.x * 256 + threadIdx.x;
    if (idx >= (size_t)NBLK*4*2*384*40) return;
    int kk = idx % 40;
    int m  = (idx / 40) % 384;
    int h  = (idx / (40*384)) % 2;
    int c  = (idx / (40*384*2)) % 4;
    int i  = idx / (40*384*2*4);
    float w = 0.f;
    if (kk < 32) {
        int k = c*32 + kk;
        if (k < 120) {
            if (m < 256) { if (m < 240) w = skip_w[(i*240+m)*120 + k]; }
            else         { int r = m - 256; if (r < 120) w = res_w[(i*120+r)*120 + k]; }
        }
    }
    bf16 hi = __float2bfloat16_rn(w);
    g_Ws2[idx] = h ? __float2bfloat16_rn(w - __bfloat162float(hi)) : hi;
}
__global__ void pack_f(const float* __restrict__ out_w, const float* __restrict__ end_w) {
    size_t idx = (size_t)blockIdx.x * 256 + threadIdx.x;
    if (idx >= (size_t)2*8*2*256*40) return;
    int kk = idx % 40;
    int m  = (idx / 40) % 256;
    int h  = (idx / (40*256)) % 2;
    int c  = (idx / (40*256*2)) % 8;
    int ws = idx / (40*256*2*8);
    float w = 0.f;
    if (kk < 32) {
        int k = c*32 + kk;
        if (ws == 0) { if (k < 240) w = out_w[m*240 + k]; }
        else         { w = end_w[m*256 + k]; }
    }
    bf16 hi = __float2bfloat16_rn(w);
    g_Wf[idx] = h ? __float2bfloat16_rn(w - __bfloat162float(hi)) : hi;
}
__global__ void pack_bias(const float* __restrict__ dil_b, const float* __restrict__ cond_b,
                          const float* __restrict__ skip_b, const float* __restrict__ res_b) {
    int idx = blockIdx.x * 256 + threadIdx.x;
    if (idx >= NBLK * 640) return;
    int j = idx % 640, i = idx / 640;
    if (j < 256) {
        int h = j >> 7, m = j & 127;
        int o = h ? (120 + m) : m;
        g_Bg2[(i*2+h)*128 + m] = (m < 120) ? (dil_b[i*240+o] + cond_b[i*240+o]) : 0.f;
    } else if (j < 512) {
        int o = j - 256;
        g_Bs[i*256 + o] = (o < 240) ? skip_b[i*240+o] : 0.f;
    } else {
        int m = j - 512;
        g_Br[i*128 + m] = (m < 120) ? res_b[i*120+m] : 0.f;
    }
}
__global__ void init_res(const float* __restrict__ wav, const float* __restrict__ wav_w,
                         const float* __restrict__ wav_b) {
    size_t idx = (size_t)blockIdx.x * 256 + threadIdx.x;
    if (idx >= (size_t)BATCH*128*TLEN) return;
    int t = idx % TLEN;
    int r = (idx / TLEN) & 127;
    int b = idx / ((size_t)TLEN * 128);
    g_res0[idx] = (r < 120) ? (wav_w[r] * wav[(size_t)b*TLEN + t] + wav_b[r]) : 0.f;
}

// ---------------- fused WaveNet block ----------------
__global__ __launch_bounds__(512, 1)
void block_mma(int blk, int d, int src, int first, const float* __restrict__ cond) {
    extern __shared__ char smr[];
    uint32_t uS = smem_u32(smr);
    int tid = threadIdx.x, w = tid >> 5, lane = tid & 31;
    int mw = w >> 1, nw = w & 1;
    int rbase = mw * 32, cbase = nw * 64;
    int b = blockIdx.y, t0 = blockIdx.x * TN;
    const float* __restrict__ rin = src ? g_res1 : g_res0;
    float* __restrict__ rout = src ? g_res0 : g_res1;

    float acc[2][8][4];
    #pragma unroll
    for (int x = 0; x < 2; x++)
        #pragma unroll
        for (int y = 0; y < 8; y++)
            #pragma unroll
            for (int q = 0; q < 4; q++) acc[x][y][q] = 0.f;

    // ======== stage 1: gate GEMM, 11 chunks of 32k ========
    #pragma unroll 1
    for (int c = 0; c < 11; c++) {
        int s = c & 1;
        char* slot = smr + s * SLOT_BYTES;
        {
            const uint4* wsrc = (const uint4*)(g_Ws1 + (size_t)(blk*11 + c)*2*256*40);
            uint4* wd = (uint4*)slot;
            #pragma unroll
            for (int q = 0; q < 5; q++) wd[tid + q*512] = wsrc[tid + q*512];
        }
        {
            bf16* Xh = (bf16*)(slot + OFF_X_IN_SLOT);
            bf16* Xl = (bf16*)(slot + OFF_X_IN_SLOT + X_HSTRIDE);
            #pragma unroll
            for (int i2 = 0; i2 < 8; i2++) {
                int e = tid + i2*512;
                int t = e & 127, k = e >> 7;
                float v = 0.f;
                if (c < 4)      { int ch = c*32 + k; int tg = t0 + t - d;
                                  if (tg >= 0) v = rin[((size_t)b*128 + ch)*TLEN + tg]; }
                else if (c < 8) { int ch = (c-4)*32 + k;
                                  v = rin[((size_t)b*128 + ch)*TLEN + t0 + t]; }
                else            { int q2 = (c-8)*32 + k;
                                  if (q2 < NMEL) v = cond[((size_t)b*NMEL + q2)*TLEN + t0 + t]; }
                bf16 hv = __float2bfloat16_rn(v);
                Xh[k*136 + t] = hv;
                Xl[k*136 + t] = __float2bfloat16_rn(v - __bfloat162float(hv));
            }
        }
        __syncthreads();
        uint32_t uW = uS + s*SLOT_BYTES;
        uint32_t uX = uW + OFF_X_IN_SLOT;
        mma_chunk<2>(acc, uW, uW + W_HSTRIDE, uX, uX + X_HSTRIDE, rbase, cbase, lane);
        __syncthreads();
    }

    // ======== gate exchange + gating ========
    float* sGsF = (float*)smr;   // [128][132] floats, region A (chunk buffers now dead)
    if (w >= 8) {
        int rb = (mw - 4) * 32;
        #pragma unroll
        for (int mt = 0; mt < 2; mt++)
            #pragma unroll
            for (int np = 0; np < 8; np++)
                #pragma unroll
                for (int hh = 0; hh < 2; hh++) {
                    int r = rb + mt*16 + (lane >> 2) + hh*8;
                    int cc = cbase + np*8 + (lane & 3)*2;
                    sGsF[r*132 + cc]     = acc[mt][np][hh*2+0];
                    sGsF[r*132 + cc + 1] = acc[mt][np][hh*2+1];
                }
    }
    __syncthreads();
    if (w < 8) {
        #pragma unroll
        for (int mt = 0; mt < 2; mt++)
            #pragma unroll
            for (int hh = 0; hh < 2; hh++) {
                int r = rbase + mt*16 + (lane >> 2) + hh*8;
                float bT = g_Bg2[(blk*2+0)*128 + r];
                float bS = g_Bg2[(blk*2+1)*128 + r];
                #pragma unroll
                for (int np = 0; np < 8; np++)
                    #pragma unroll
                    for (int e = 0; e < 2; e++) {
                        int cc = cbase + np*8 + (lane & 3)*2 + e;
                        float a = acc[mt][np][hh*2+e] + bT;
                        float g = sGsF[r*132 + cc] + bS;
                        float th = 1.f - __fdividef(2.f, __expf(2.f*a) + 1.f);
                        float sg = __fdividef(1.f, 1.f + __expf(-g));
                        float v = th * sg;
                        bf16 hv = __float2bfloat16_rn(v);
                        *(bf16*)(smr + OFF_XG + (r*136 + cc)*2) = hv;
                        *(bf16*)(smr + OFF_XG + XG_HSTRIDE + (r*136 + cc)*2) =
                            __float2bfloat16_rn(v - __bfloat162float(hv));
                    }
            }
    }
    __syncthreads();

    // ======== stage 2a: skip GEMM (M=256, K=128 in 4 chunks) ========
    #pragma unroll
    for (int x = 0; x < 2; x++)
        #pragma unroll
        for (int y = 0; y < 8; y++)
            #pragma unroll
            for (int q = 0; q < 4; q++) acc[x][y][q] = 0.f;
    #pragma unroll 1
    for (int c = 0; c < 4; c++) {
        int s = c & 1;
        char* slot = smr + s * SLOT_BYTES;
        {
            const uint4* wsrc = (const uint4*)(g_Ws2 + (size_t)(blk*4 + c)*2*384*40);
            uint4* wd = (uint4*)slot;
            for (int q = tid; q < 1280; q += 512) { wd[q] = wsrc[q]; wd[1280 + q] = wsrc[1920 + q]; }
        }
        __syncthreads();
        uint32_t uW = uS + s*SLOT_BYTES;
        uint32_t uXG = uS + OFF_XG + c*32*272;
        mma_chunk<2>(acc, uW, uW + W_HSTRIDE, uXG, uXG + XG_HSTRIDE, rbase, cbase, lane);
        __syncthreads();
    }
    // skip epilogue: 2 column phases via smem staging [256][68]
    {
        float* stg = (float*)smr;
        #pragma unroll 1
        for (int p = 0; p < 2; p++) {
            if (nw == p) {
                #pragma unroll
                for (int mt = 0; mt < 2; mt++)
                    #pragma unroll
                    for (int np = 0; np < 8; np++)
                        #pragma unroll
                        for (int hh = 0; hh < 2; hh++) {
                            int r = rbase + mt*16 + (lane >> 2) + hh*8;
                            int cc = np*8 + (lane & 3)*2;
                            stg[r*68 + cc]     = acc[mt][np][hh*2+0];
                            stg[r*68 + cc + 1] = acc[mt][np][hh*2+1];
                        }
            }
            __syncthreads();
            {
                int r = tid >> 1, half = tid & 1;
                float bias = g_Bs[blk*256 + r];
                float* dst = g_skip + ((size_t)b*256 + r)*TLEN + t0 + p*64 + half*32;
                const float* st = stg + r*68 + half*32;
                #pragma unroll
                for (int j = 0; j < 8; j++) {
                    float4 v = *(const float4*)(st + j*4);
                    v.x += bias; v.y += bias; v.z += bias; v.w += bias;
                    if (!first) {
                        float4 o = *(const float4*)(dst + j*4);
                        v.x += o.x; v.y += o.y; v.z += o.z; v.w += o.w;
                    }
                    *(float4*)(dst + j*4) = v;
                }
            }
            __syncthreads();
        }
    }

    // ======== stage 2b: residual GEMM (M=128, K=128) ========
    #pragma unroll
    for (int y = 0; y < 8; y++)
        #pragma unroll
        for (int q = 0; q < 4; q++) acc[0][y][q] = 0.f;
    int rb2 = mw * 16;
    #pragma unroll 1
    for (int c = 0; c < 4; c++) {
        int s = c & 1;
        char* slot = smr + s * SLOT_BYTES;
        {
            const uint4* wsrc = (const uint4*)(g_Ws2 + (size_t)(blk*4 + c)*2*384*40);
            uint4* wd = (uint4*)slot;
            for (int q = tid; q < 640; q += 512) { wd[q] = wsrc[1280 + q]; wd[640 + q] = wsrc[3200 + q]; }
        }
        __syncthreads();
        uint32_t uW = uS + s*SLOT_BYTES;
        uint32_t uXG = uS + OFF_XG + c*32*272;
        mma_chunk<1>(acc, uW, uW + 10240, uXG, uXG + XG_HSTRIDE, rb2, cbase, lane);
        __syncthreads();
    }
    // residual epilogue: staging [128][68], add old residual + bias
    {
        float* stg = (float*)smr;
        #pragma unroll 1
        for (int p = 0; p < 2; p++) {
            if (nw == p) {
                #pragma unroll
                for (int np = 0; np < 8; np++)
                    #pragma unroll
                    for (int hh = 0; hh < 2; hh++) {
                        int r = rb2 + (lane >> 2) + hh*8;
                        int cc = np*8 + (lane & 3)*2;
                        stg[r*68 + cc]     = acc[0][np][hh*2+0];
                        stg[r*68 + cc + 1] = acc[0][np][hh*2+1];
                    }
            }
            __syncthreads();
            {
                int r = tid >> 2, qd = tid & 3;
                float bias = g_Br[blk*128 + r];
                const float* pin = rin + ((size_t)b*128 + r)*TLEN + t0 + p*64 + qd*16;
                float* pout = rout + ((size_t)b*128 + r)*TLEN + t0 + p*64 + qd*16;
                const float* st = stg + r*68 + qd*16;
                #pragma unroll
                for (int j = 0; j < 4; j++) {
                    float4 v = *(const float4*)(st + j*4);
                    float4 o = *(const float4*)(pin + j*4);
                    v.x += bias + o.x; v.y += bias + o.y;
                    v.z += bias + o.z; v.w += bias + o.w;
                    *(float4*)(pout + j*4) = v;
                }
            }
            __syncthreads();
        }
    }
}

// ---------------- final GEMMs (relu-in, M=256, K=256) ----------------
__global__ __launch_bounds__(512, 1)
void final_mma(int which, const float* __restrict__ bias, float* __restrict__ dst_ext) {
    extern __shared__ char smr[];
    uint32_t uS = smem_u32(smr);
    int tid = threadIdx.x, w = tid >> 5, lane = tid & 31;
    int mw = w >> 1, nw = w & 1;
    int rbase = mw * 32, cbase = nw * 64;
    int b = blockIdx.y, t0 = blockIdx.x * TN;
    const float* __restrict__ in = which ? g_obuf : g_skip;
    float* __restrict__ dst = which ? dst_ext : g_obuf;

    float acc[2][8][4];
    #pragma unroll
    for (int x = 0; x < 2; x++)
        #pragma unroll
        for (int y = 0; y < 8; y++)
            #pragma unroll
            for (int q = 0; q < 4; q++) acc[x][y][q] = 0.f;

    #pragma unroll 1
    for (int c = 0; c < 8; c++) {
        int s = c & 1;
        char* slot = smr + s * SLOT_BYTES;
        {
            const uint4* wsrc = (const uint4*)(g_Wf + ((size_t)which*8 + c)*2*256*40);
            uint4* wd = (uint4*)slot;
            #pragma unroll
            for (int q = 0; q < 5; q++) wd[tid + q*512] = wsrc[tid + q*512];
        }
        {
            bf16* Xh = (bf16*)(slot + OFF_X_IN_SLOT);
            bf16* Xl = (bf16*)(slot + OFF_X_IN_SLOT + X_HSTRIDE);
            #pragma unroll
            for (int i2 = 0; i2 < 8; i2++) {
                int e = tid + i2*512;
                int t = e & 127, k = e >> 7;
                int ch = c*32 + k;
                float v = fmaxf(in[((size_t)b*256 + ch)*TLEN + t0 + t], 0.f);
                bf16 hv = __float2bfloat16_rn(v);
                Xh[k*136 + t] = hv;
                Xl[k*136 + t] = __float2bfloat16_rn(v - __bfloat162float(hv));
            }
        }
        __syncthreads();
        uint32_t uW = uS + s*SLOT_BYTES;
        uint32_t uX = uW + OFF_X_IN_SLOT;
        mma_chunk<2>(acc, uW, uW + W_HSTRIDE, uX, uX + X_HSTRIDE, rbase, cbase, lane);
        __syncthreads();
    }

    float* stg = (float*)smr;
    #pragma unroll 1
    for (int p = 0; p < 2; p++) {
        if (nw == p) {
            #pragma unroll
            for (int mt = 0; mt < 2; mt++)
                #pragma unroll
                for (int np = 0; np < 8; np++)
                    #pragma unroll
                    for (int hh = 0; hh < 2; hh++) {
                        int r = rbase + mt*16 + (lane >> 2) + hh*8;
                        int cc = np*8 + (lane & 3)*2;
                        stg[r*68 + cc]     = acc[mt][np][hh*2+0];
                        stg[r*68 + cc + 1] = acc[mt][np][hh*2+1];
                    }
        }
        __syncthreads();
        {
            int r = tid >> 1, half = tid & 1;
            float bi = bias[r];
            float* dp = dst + ((size_t)b*256 + r)*TLEN + t0 + p*64 + half*32;
            const float* st = stg + r*68 + half*32;
            #pragma unroll
            for (int j = 0; j < 8; j++) {
                float4 v = *(const float4*)(st + j*4);
                v.x += bi; v.y += bi; v.z += bi; v.w += bi;
                *(float4*)(dp + j*4) = v;
            }
        }
        __syncthreads();
    }
}

// ---------------- launch ----------------
extern "C" void kernel_launch(void* const* d_in, const int* in_sizes, int n_in,
                              void* d_out, int out_size) {
    const float* wav    = (const float*)d_in[0];
    const float* cond   = (const float*)d_in[1];
    const float* wav_w  = (const float*)d_in[2];
    const float* wav_b  = (const float*)d_in[3];
    const float* cond_w = (const float*)d_in[4];
    const float* cond_b = (const float*)d_in[5];
    const float* dil_w  = (const float*)d_in[6];
    const float* dil_b  = (const float*)d_in[7];
    const float* skip_w = (const float*)d_in[8];
    const float* skip_b = (const float*)d_in[9];
    const float* res_w  = (const float*)d_in[10];
    const float* res_b  = (const float*)d_in[11];
    const float* out_w  = (const float*)d_in[12];
    const float* out_b  = (const float*)d_in[13];
    const float* end_w  = (const float*)d_in[14];
    const float* end_b  = (const float*)d_in[15];

    cudaFuncSetAttribute(block_mma, cudaFuncAttributeMaxDynamicSharedMemorySize, SMEM_BLK);
    cudaFuncSetAttribute(final_mma, cudaFuncAttributeMaxDynamicSharedMemorySize, SMEM_FIN);

    pack_s1<<<(int)(((size_t)NBLK*11*2*256*40 + 255)/256), 256>>>(dil_w, cond_w);
    pack_s2<<<(int)(((size_t)NBLK*4*2*384*40 + 255)/256), 256>>>(skip_w, res_w);
    pack_f<<<(int)(((size_t)2*8*2*256*40 + 255)/256), 256>>>(out_w, end_w);
    pack_bias<<<(NBLK*640 + 255)/256, 256>>>(dil_b, cond_b, skip_b, res_b);
    init_res<<<(int)(((size_t)BATCH*128*TLEN + 255)/256), 256>>>(wav, wav_w, wav_b);

    dim3 grid(TLEN / TN, BATCH);
    for (int i = 0; i < NBLK; i++)
        block_mma<<<grid, 512, SMEM_BLK>>>(i, 1 << (i % 8), i & 1, (i == 0) ? 1 : 0, cond);
    final_mma<<<grid, 512, SMEM_FIN>>>(0, out_b, nullptr);
    final_mma<<<grid, 512, SMEM_FIN>>>(1, end_b, (float*)d_out);
}

// round 9
// speedup vs baseline: 1.9080x; 1.0190x over previous
#include <cuda_runtime.h>
#include <cuda_bf16.h>
#include <cstdint>

#define TLEN 32768
#define BATCH 4
#define NMEL 80
#define NBLK 16
#define TN 128
#define RSTRIDE (TLEN + 256)

#define SLOT_BYTES 58368
#define OFF_X_IN_SLOT 40960
#define X_HSTRIDE 8704
#define W_HSTRIDE 20480
#define OFF_XG 116736
#define XG_HSTRIDE 34816
#define SMEM_BLK 186368

#define FSLOT 74752
#define OFF_RAW 58368
#define SMEM_FIN 149504

typedef __nv_bfloat16 bf16;

// ---------------- device scratch ----------------
__device__ float g_resF[2][(size_t)BATCH*128*TLEN];     // fp32 residual chain (ping-pong)
__device__ bf16  g_R[(size_t)8*BATCH*128*RSTRIDE];      // [pp][shifted][plane] bf16 residual
__device__ bf16  g_cnd[2][(size_t)BATCH*96*TLEN];       // cond hi/lo, rows 80..95 zero
__device__ float g_skip[(size_t)BATCH*256*TLEN];
__device__ float g_obuf[(size_t)BATCH*256*TLEN];

__device__ bf16 g_Ws1[(size_t)NBLK*11*2*256*40];
__device__ bf16 g_W2s[(size_t)NBLK*4*2*256*40];
__device__ bf16 g_W2r[(size_t)NBLK*4*2*128*40];
__device__ bf16 g_Wf [(size_t)2*8*2*256*40];
__device__ float g_Bg2[NBLK*2*128];
__device__ float g_Bs[NBLK*256];
__device__ float g_Br[NBLK*128];

#define RPLANE(pp,sh,pl) (g_R + ((((size_t)(pp)*2+(sh))*2+(pl)) * ((size_t)BATCH*128*RSTRIDE)))

// ---------------- helpers ----------------
__device__ __forceinline__ uint32_t smem_u32(const void* p) {
    uint32_t a;
    asm("{ .reg .u64 t; cvta.to.shared.u64 t, %1; cvt.u32.u64 %0, t; }" : "=r"(a) : "l"(p));
    return a;
}
__device__ __forceinline__ void cpa16(uint32_t dst, const void* src) {
    asm volatile("cp.async.cg.shared.global [%0], [%1], 16;" :: "r"(dst), "l"(src));
}
#define CP_COMMIT() asm volatile("cp.async.commit_group;" ::: "memory")
#define CP_WAIT1()  asm volatile("cp.async.wait_group 1;" ::: "memory")
__device__ __forceinline__ void mma16816(float* d, const uint32_t* a, const uint32_t* b) {
    asm volatile("mma.sync.aligned.m16n8k16.row.col.f32.bf16.bf16.f32 "
        "{%0,%1,%2,%3}, {%4,%5,%6,%7}, {%8,%9}, {%0,%1,%2,%3};"
        : "+f"(d[0]), "+f"(d[1]), "+f"(d[2]), "+f"(d[3])
        : "r"(a[0]), "r"(a[1]), "r"(a[2]), "r"(a[3]), "r"(b[0]), "r"(b[1]));
}
__device__ __forceinline__ void ldsm4(uint32_t* r, uint32_t addr) {
    asm volatile("ldmatrix.sync.aligned.m8n8.x4.shared.b16 {%0,%1,%2,%3}, [%4];"
        : "=r"(r[0]), "=r"(r[1]), "=r"(r[2]), "=r"(r[3]) : "r"(addr));
}
__device__ __forceinline__ void ldsm4t(uint32_t* r, uint32_t addr) {
    asm volatile("ldmatrix.sync.aligned.m8n8.x4.trans.shared.b16 {%0,%1,%2,%3}, [%4];"
        : "=r"(r[0]), "=r"(r[1]), "=r"(r[2]), "=r"(r[3]) : "r"(addr));
}

template<int MT>
__device__ __forceinline__ void mma_chunk(float (*acc)[8][4],
    uint32_t uWh, uint32_t uWl, uint32_t uXh, uint32_t uXl,
    int rbase, int cbase, int lane)
{
    int lt = lane >> 3, lr = lane & 7;
    #pragma unroll
    for (int ks = 0; ks < 2; ks++) {
        uint32_t aH[MT][4], aL[MT][4];
        #pragma unroll
        for (int mt = 0; mt < MT; mt++) {
            uint32_t off = ((uint32_t)(rbase + mt*16 + (lt & 1)*8 + lr) * 40
                            + ks*16 + (lt >> 1)*8) * 2;
            ldsm4(aH[mt], uWh + off);
            ldsm4(aL[mt], uWl + off);
        }
        uint32_t krow = ks*16 + (lt & 1)*8 + lr;
        #pragma unroll
        for (int np = 0; np < 4; np++) {
            uint32_t boff = (krow*136 + (uint32_t)(cbase + np*16 + (lt >> 1)*8)) * 2;
            uint32_t bH[4], bL[4];
            ldsm4t(bH, uXh + boff);
            ldsm4t(bL, uXl + boff);
            #pragma unroll
            for (int mt = 0; mt < MT; mt++) {
                #pragma unroll
                for (int nh = 0; nh < 2; nh++) {
                    mma16816(acc[mt][np*2+nh], aH[mt], &bH[nh*2]);
                    mma16816(acc[mt][np*2+nh], aL[mt], &bH[nh*2]);
                    mma16816(acc[mt][np*2+nh], aH[mt], &bL[nh*2]);
                }
            }
        }
    }
}

// ---------------- pack kernels ----------------
__global__ void pack_s1(const float* __restrict__ dil_w, const float* __restrict__ cond_w) {
    size_t idx = (size_t)blockIdx.x * 256 + threadIdx.x;
    if (idx >= (size_t)NBLK*11*2*256*40) return;
    int kk = idx % 40;
    int m  = (idx / 40) % 256;
    int h  = (idx / (40*256)) % 2;
    int c  = (idx / (40*256*2)) % 11;
    int i  = idx / (40*256*2*11);
    float w = 0.f;
    if (kk < 32) {
        int k = c*32 + kk;
        int o = (m < 128) ? m : (120 + (m - 128));
        bool ov = (m < 128) ? (m < 120) : (m - 128 < 120);
        if (ov) {
            if (k < 128)      { if (k < 120) w = dil_w[((i*240+o)*120 + k)*2 + 0]; }
            else if (k < 256) { int q = k - 128; if (q < 120) w = dil_w[((i*240+o)*120 + q)*2 + 1]; }
            else if (k < 336) { int q = k - 256; if (q < NMEL) w = cond_w[(i*240+o)*80 + q]; }
        }
    }
    bf16 hi = __float2bfloat16_rn(w);
    g_Ws1[idx] = h ? __float2bfloat16_rn(w - __bfloat162float(hi)) : hi;
}
__global__ void pack_s2(const float* __restrict__ skip_w, const float* __restrict__ res_w) {
    size_t idx = (size_t)blockIdx.x * 256 + threadIdx.x;
    if (idx >= (size_t)NBLK*4*2*384*40) return;
    int kk = idx % 40;
    int m  = (idx / 40) % 384;
    int h  = (idx / (40*384)) % 2;
    int c  = (idx / (40*384*2)) % 4;
    int i  = idx / (40*384*2*4);
    float w = 0.f;
    if (kk < 32) {
        int k = c*32 + kk;
        if (k < 120) {
            if (m < 256) { if (m < 240) w = skip_w[(i*240+m)*120 + k]; }
            else         { int r = m - 256; if (r < 120) w = res_w[(i*120+r)*120 + k]; }
        }
    }
    bf16 hi = __float2bfloat16_rn(w);
    bf16 v = h ? __float2bfloat16_rn(w - __bfloat162float(hi)) : hi;
    if (m < 256) g_W2s[((((size_t)i*4+c)*2+h)*256 + m)*40 + kk] = v;
    else         g_W2r[((((size_t)i*4+c)*2+h)*128 + (m-256))*40 + kk] = v;
}
__global__ void pack_f(const float* __restrict__ out_w, const float* __restrict__ end_w) {
    size_t idx = (size_t)blockIdx.x * 256 + threadIdx.x;
    if (idx >= (size_t)2*8*2*256*40) return;
    int kk = idx % 40;
    int m  = (idx / 40) % 256;
    int h  = (idx / (40*256)) % 2;
    int c  = (idx / (40*256*2)) % 8;
    int ws = idx / (40*256*2*8);
    float w = 0.f;
    if (kk < 32) {
        int k = c*32 + kk;
        if (ws == 0) { if (k < 240) w = out_w[m*240 + k]; }
        else         { w = end_w[m*256 + k]; }
    }
    bf16 hi = __float2bfloat16_rn(w);
    g_Wf[idx] = h ? __float2bfloat16_rn(w - __bfloat162float(hi)) : hi;
}
__global__ void pack_bias(const float* __restrict__ dil_b, const float* __restrict__ cond_b,
                          const float* __restrict__ skip_b, const float* __restrict__ res_b) {
    int idx = blockIdx.x * 256 + threadIdx.x;
    if (idx >= NBLK * 640) return;
    int j = idx % 640, i = idx / 640;
    if (j < 256) {
        int h = j >> 7, m = j & 127;
        int o = h ? (120 + m) : m;
        g_Bg2[(i*2+h)*128 + m] = (m < 120) ? (dil_b[i*240+o] + cond_b[i*240+o]) : 0.f;
    } else if (j < 512) {
        int o = j - 256;
        g_Bs[i*256 + o] = (o < 240) ? skip_b[i*240+o] : 0.f;
    } else {
        int m = j - 512;
        g_Br[i*128 + m] = (m < 120) ? res_b[i*120+m] : 0.f;
    }
}
__global__ void init_resA(const float* __restrict__ wav, const float* __restrict__ wav_w,
                          const float* __restrict__ wav_b) {
    size_t idx = (size_t)blockIdx.x * 256 + threadIdx.x;
    if (idx >= (size_t)BATCH*128*TLEN) return;
    int t = idx % TLEN;
    int r = (idx / TLEN) & 127;
    int b = idx / ((size_t)TLEN * 128);
    float v = (r < 120) ? (wav_w[r] * wav[(size_t)b*TLEN + t] + wav_b[r]) : 0.f;
    g_resF[0][idx] = v;
    bf16 h = __float2bfloat16_rn(v);
    bf16 l = __float2bfloat16_rn(v - __bfloat162float(h));
    size_t base = (size_t)(b*128 + r)*RSTRIDE;
    RPLANE(0,0,0)[base + 128 + t] = h;
    RPLANE(0,0,1)[base + 128 + t] = l;
    RPLANE(0,1,0)[base + 129 + t] = h;   // shifted by d0 = 1
    RPLANE(0,1,1)[base + 129 + t] = l;
    if (t == 0) {
        RPLANE(0,1,0)[base + 128] = __float2bfloat16_rn(0.f);
        RPLANE(0,1,1)[base + 128] = __float2bfloat16_rn(0.f);
    }
}
__global__ void init_cnd(const float* __restrict__ cond) {
    size_t idx = (size_t)blockIdx.x * 256 + threadIdx.x;
    if (idx >= (size_t)BATCH*96*TLEN) return;
    int t = idx % TLEN;
    int q = (idx / TLEN) % 96;
    int b = idx / ((size_t)TLEN * 96);
    float v = (q < NMEL) ? cond[((size_t)b*NMEL + q)*TLEN + t] : 0.f;
    bf16 h = __float2bfloat16_rn(v);
    g_cnd[0][idx] = h;
    g_cnd[1][idx] = __float2bfloat16_rn(v - __bfloat162float(h));
}

// ---------------- fused WaveNet block ----------------
__global__ __launch_bounds__(512, 1)
void block_mma(int blk, int dnext, int p, int first, int last) {
    extern __shared__ char smr[];
    uint32_t uS = smem_u32(smr);
    int tid = threadIdx.x, w = tid >> 5, lane = tid & 31;
    int mw = w >> 1, nw = w & 1;
    int rbase = mw * 32, cbase = nw * 64;
    int b = blockIdx.y, t0 = blockIdx.x * TN;

    float acc[2][8][4];
    #pragma unroll
    for (int x = 0; x < 2; x++)
        #pragma unroll
        for (int y = 0; y < 8; y++)
            #pragma unroll
            for (int q = 0; q < 4; q++) acc[x][y][q] = 0.f;

    // -------- stage-1 prefetch --------
    auto pf1 = [&](int c, int s) {
        uint32_t uSlot = uS + s*SLOT_BYTES;
        const char* ws = (const char*)g_Ws1 + (size_t)(blk*11 + c)*40960;
        #pragma unroll
        for (int q = 0; q < 5; q++) {
            int e = tid + q*512;
            cpa16(uSlot + e*16, ws + (size_t)e*16);
        }
        int row = tid >> 4, seg = tid & 15;
        uint32_t xd = uSlot + OFF_X_IN_SLOT + row*272 + seg*16;
        const char *sH, *sL;
        if (c < 8) {
            int sh = (c < 4) ? 1 : 0;
            int ch = (c & 3)*32 + row;
            size_t off = ((size_t)(b*128 + ch)*RSTRIDE + 128 + t0)*2 + seg*16;
            sH = (const char*)RPLANE(p, sh, 0) + off;
            sL = (const char*)RPLANE(p, sh, 1) + off;
        } else {
            int q2 = (c - 8)*32 + row;
            size_t off = ((size_t)(b*96 + q2)*TLEN + t0)*2 + seg*16;
            sH = (const char*)g_cnd[0] + off;
            sL = (const char*)g_cnd[1] + off;
        }
        cpa16(xd, sH);
        cpa16(xd + X_HSTRIDE, sL);
    };

    pf1(0, 0); CP_COMMIT();
    pf1(1, 1); CP_COMMIT();
    #pragma unroll 1
    for (int c = 0; c < 11; c++) {
        int s = c & 1;
        CP_WAIT1(); __syncthreads();
        uint32_t uW = uS + s*SLOT_BYTES;
        uint32_t uX = uW + OFF_X_IN_SLOT;
        mma_chunk<2>(acc, uW, uW + W_HSTRIDE, uX, uX + X_HSTRIDE, rbase, cbase, lane);
        __syncthreads();
        if (c + 2 < 11) pf1(c + 2, s);
        CP_COMMIT();
    }

    // -------- gate exchange + gating --------
    float* sGsF = (float*)smr;   // [128][132]
    if (w >= 8) {
        int rb = (mw - 4) * 32;
        #pragma unroll
        for (int mt = 0; mt < 2; mt++)
            #pragma unroll
            for (int np = 0; np < 8; np++)
                #pragma unroll
                for (int hh = 0; hh < 2; hh++) {
                    int r = rb + mt*16 + (lane >> 2) + hh*8;
                    int cc = cbase + np*8 + (lane & 3)*2;
                    sGsF[r*132 + cc]     = acc[mt][np][hh*2+0];
                    sGsF[r*132 + cc + 1] = acc[mt][np][hh*2+1];
                }
    }
    __syncthreads();
    if (w < 8) {
        #pragma unroll
        for (int mt = 0; mt < 2; mt++)
            #pragma unroll
            for (int hh = 0; hh < 2; hh++) {
                int r = rbase + mt*16 + (lane >> 2) + hh*8;
                float bT = g_Bg2[(blk*2+0)*128 + r];
                float bS = g_Bg2[(blk*2+1)*128 + r];
                #pragma unroll
                for (int np = 0; np < 8; np++)
                    #pragma unroll
                    for (int e = 0; e < 2; e++) {
                        int cc = cbase + np*8 + (lane & 3)*2 + e;
                        float a = acc[mt][np][hh*2+e] + bT;
                        float g = sGsF[r*132 + cc] + bS;
                        float th = 1.f - __fdividef(2.f, __expf(2.f*a) + 1.f);
                        float sg = __fdividef(1.f, 1.f + __expf(-g));
                        float v = th * sg;
                        bf16 hv = __float2bfloat16_rn(v);
                        *(bf16*)(smr + OFF_XG + (r*136 + cc)*2) = hv;
                        *(bf16*)(smr + OFF_XG + XG_HSTRIDE + (r*136 + cc)*2) =
                            __float2bfloat16_rn(v - __bfloat162float(hv));
                    }
            }
    }
    __syncthreads();

    // -------- stage 2a: skip GEMM --------
    #pragma unroll
    for (int x = 0; x < 2; x++)
        #pragma unroll
        for (int y = 0; y < 8; y++)
            #pragma unroll
            for (int q = 0; q < 4; q++) acc[x][y][q] = 0.f;

    auto pf2a = [&](int c, int s) {
        const char* ws = (const char*)g_W2s + (size_t)(blk*4 + c)*40960;
        uint32_t uSlot = uS + s*SLOT_BYTES;
        #pragma unroll
        for (int q = 0; q < 5; q++) {
            int e = tid + q*512;
            cpa16(uSlot + e*16, ws + (size_t)e*16);
        }
    };
    pf2a(0, 0); CP_COMMIT();
    pf2a(1, 1); CP_COMMIT();
    #pragma unroll 1
    for (int c = 0; c < 4; c++) {
        int s = c & 1;
        CP_WAIT1(); __syncthreads();
        uint32_t uW = uS + s*SLOT_BYTES;
        uint32_t uXG = uS + OFF_XG + c*8704;
        mma_chunk<2>(acc, uW, uW + W_HSTRIDE, uXG, uXG + XG_HSTRIDE, rbase, cbase, lane);
        __syncthreads();
        if (c + 2 < 4) pf2a(c + 2, s);
        CP_COMMIT();
    }

    // skip epilogue
    {
        float* stg = (float*)smr;
        #pragma unroll 1
        for (int p2 = 0; p2 < 2; p2++) {
            if (nw == p2) {
                #pragma unroll
                for (int mt = 0; mt < 2; mt++)
                    #pragma unroll
                    for (int np = 0; np < 8; np++)
                        #pragma unroll
                        for (int hh = 0; hh < 2; hh++) {
                            int r = rbase + mt*16 + (lane >> 2) + hh*8;
                            int cc = np*8 + (lane & 3)*2;
                            stg[r*68 + cc]     = acc[mt][np][hh*2+0];
                            stg[r*68 + cc + 1] = acc[mt][np][hh*2+1];
                        }
            }
            __syncthreads();
            {
                int r = tid >> 1, half = tid & 1;
                float bias = g_Bs[blk*256 + r];
                float* dst = g_skip + ((size_t)b*256 + r)*TLEN + t0 + p2*64 + half*32;
                const float* st = stg + r*68 + half*32;
                #pragma unroll
                for (int j = 0; j < 8; j++) {
                    float4 v = *(const float4*)(st + j*4);
                    v.x += bias; v.y += bias; v.z += bias; v.w += bias;
                    if (!first) {
                        float4 o = *(const float4*)(dst + j*4);
                        v.x += o.x; v.y += o.y; v.z += o.z; v.w += o.w;
                    }
                    *(float4*)(dst + j*4) = v;
                }
            }
            __syncthreads();
        }
    }

    // -------- stage 2b: residual GEMM --------
    #pragma unroll
    for (int y = 0; y < 8; y++)
        #pragma unroll
        for (int q = 0; q < 4; q++) acc[0][y][q] = 0.f;
    int rb2 = mw * 16;

    auto pf2b = [&](int c, int s) {
        const char* ws = (const char*)g_W2r + (size_t)(blk*4 + c)*20480;
        uint32_t uSlot = uS + s*SLOT_BYTES;
        #pragma unroll
        for (int q = 0; q < 3; q++) {
            int e = tid + q*512;
            if (e < 1280) cpa16(uSlot + e*16, ws + (size_t)e*16);
        }
    };
    pf2b(0, 0); CP_COMMIT();
    pf2b(1, 1); CP_COMMIT();
    #pragma unroll 1
    for (int c = 0; c < 4; c++) {
        int s = c & 1;
        CP_WAIT1(); __syncthreads();
        uint32_t uW = uS + s*SLOT_BYTES;
        uint32_t uXG = uS + OFF_XG + c*8704;
        mma_chunk<1>(acc, uW, uW + 10240, uXG, uXG + XG_HSTRIDE, rb2, cbase, lane);
        __syncthreads();
        if (c + 2 < 4) pf2b(c + 2, s);
        CP_COMMIT();
    }

    // residual epilogue
    {
        float* stg = (float*)smr;
        #pragma unroll 1
        for (int p2 = 0; p2 < 2; p2++) {
            if (nw == p2) {
                #pragma unroll
                for (int np = 0; np < 8; np++)
                    #pragma unroll
                    for (int hh = 0; hh < 2; hh++) {
                        int r = rb2 + (lane >> 2) + hh*8;
                        int cc = np*8 + (lane & 3)*2;
                        stg[r*68 + cc]     = acc[0][np][hh*2+0];
                        stg[r*68 + cc + 1] = acc[0][np][hh*2+1];
                    }
            }
            __syncthreads();
            {
                int r = tid >> 2, qd = tid & 3;
                int ct = t0 + p2*64 + qd*16;
                float bias = g_Br[blk*128 + r];
                size_t fidx = (size_t)(b*128 + r)*TLEN + ct;
                const float* oldp = g_resF[p] + fidx;
                float* newp = g_resF[1-p] + fidx;
                const float* st = stg + r*68 + qd*16;
                __align__(16) float v[16];
                #pragma unroll
                for (int j = 0; j < 4; j++) {
                    float4 sv = *(const float4*)(st + j*4);
                    float4 ov = *(const float4*)(oldp + j*4);
                    v[j*4+0] = sv.x + bias + ov.x;
                    v[j*4+1] = sv.y + bias + ov.y;
                    v[j*4+2] = sv.z + bias + ov.z;
                    v[j*4+3] = sv.w + bias + ov.w;
                    *(float4*)(newp + j*4) = make_float4(v[j*4+0], v[j*4+1], v[j*4+2], v[j*4+3]);
                }
                __align__(16) bf16 hv[16], lv[16];
                #pragma unroll
                for (int j = 0; j < 16; j++) {
                    hv[j] = __float2bfloat16_rn(v[j]);
                    lv[j] = __float2bfloat16_rn(v[j] - __bfloat162float(hv[j]));
                }
                size_t rb_ = (size_t)(b*128 + r)*RSTRIDE + 128 + ct;
                bf16* dH = RPLANE(1-p,0,0) + rb_;
                bf16* dL = RPLANE(1-p,0,1) + rb_;
                ((uint4*)dH)[0] = ((uint4*)hv)[0]; ((uint4*)dH)[1] = ((uint4*)hv)[1];
                ((uint4*)dL)[0] = ((uint4*)lv)[0]; ((uint4*)dL)[1] = ((uint4*)lv)[1];
                if (!last) {
                    bf16* sH = RPLANE(1-p,1,0) + rb_ + dnext;
                    bf16* sL = RPLANE(1-p,1,1) + rb_ + dnext;
                    if ((dnext & 7) == 0) {
                        ((uint4*)sH)[0] = ((uint4*)hv)[0]; ((uint4*)sH)[1] = ((uint4*)hv)[1];
                        ((uint4*)sL)[0] = ((uint4*)lv)[0]; ((uint4*)sL)[1] = ((uint4*)lv)[1];
                    } else {
                        #pragma unroll
                        for (int j = 0; j < 16; j++) { sH[j] = hv[j]; sL[j] = lv[j]; }
                    }
                }
            }
            __syncthreads();
        }
        // zero leading cols of shifted plane (t0 == 0 tile only)
        if (t0 == 0 && !last) {
            bf16 z = __float2bfloat16_rn(0.f);
            for (int e = tid; e < 128*dnext; e += 512) {
                int r = e / dnext, cc = e - r*dnext;
                size_t ix = (size_t)(b*128 + r)*RSTRIDE + 128 + cc;
                RPLANE(1-p,1,0)[ix] = z;
                RPLANE(1-p,1,1)[ix] = z;
            }
        }
    }
}

// ---------------- final GEMMs (relu-in, M=256, K=256) ----------------
__global__ __launch_bounds__(512, 1)
void final_mma(int which, const float* __restrict__ bias, float* __restrict__ dst_ext) {
    extern __shared__ char smr[];
    uint32_t uS = smem_u32(smr);
    int tid = threadIdx.x, w = tid >> 5, lane = tid & 31;
    int mw = w >> 1, nw = w & 1;
    int rbase = mw * 32, cbase = nw * 64;
    int b = blockIdx.y, t0 = blockIdx.x * TN;
    const float* __restrict__ in = which ? g_obuf : g_skip;
    float* __restrict__ dst = which ? dst_ext : g_obuf;

    float acc[2][8][4];
    #pragma unroll
    for (int x = 0; x < 2; x++)
        #pragma unroll
        for (int y = 0; y < 8; y++)
            #pragma unroll
            for (int q = 0; q < 4; q++) acc[x][y][q] = 0.f;

    auto pff = [&](int c, int s) {
        uint32_t uSlot = uS + s*FSLOT;
        const char* ws = (const char*)g_Wf + ((size_t)which*8 + c)*40960;
        #pragma unroll
        for (int q = 0; q < 5; q++) {
            int e = tid + q*512;
            cpa16(uSlot + e*16, ws + (size_t)e*16);
        }
        // X raw: 32 rows x 128 floats = 16384B -> 1024 cp.async (2 per thread)
        #pragma unroll
        for (int q = 0; q < 2; q++) {
            int e = tid + q*512;
            int row = e >> 5, seg = e & 31;
            size_t off = ((size_t)(b*256 + c*32 + row)*TLEN + t0)*4 + seg*16;
            cpa16(uSlot + OFF_RAW + row*512 + seg*16, (const char*)in + off);
        }
    };

    pff(0, 0); CP_COMMIT();
    pff(1, 1); CP_COMMIT();
    #pragma unroll 1
    for (int c = 0; c < 8; c++) {
        int s = c & 1;
        CP_WAIT1(); __syncthreads();
        float* raw = (float*)(smr + s*FSLOT + OFF_RAW);
        bf16* Xh = (bf16*)(smr + s*FSLOT + OFF_X_IN_SLOT);
        bf16* Xl = (bf16*)(smr + s*FSLOT + OFF_X_IN_SLOT + X_HSTRIDE);
        #pragma unroll
        for (int i2 = 0; i2 < 8; i2++) {
            int e = tid + i2*512;
            int t = e & 127, k = e >> 7;
            float v = fmaxf(raw[k*128 + t], 0.f);
            bf16 hv = __float2bfloat16_rn(v);
            Xh[k*136 + t] = hv;
            Xl[k*136 + t] = __float2bfloat16_rn(v - __bfloat162float(hv));
        }
        __syncthreads();
        uint32_t uW = uS + s*FSLOT;
        uint32_t uX = uW + OFF_X_IN_SLOT;
        mma_chunk<2>(acc, uW, uW + W_HSTRIDE, uX, uX + X_HSTRIDE, rbase, cbase, lane);
        __syncthreads();
        if (c + 2 < 8) pff(c + 2, s);
        CP_COMMIT();
    }

    float* stg = (float*)smr;
    #pragma unroll 1
    for (int p2 = 0; p2 < 2; p2++) {
        if (nw == p2) {
            #pragma unroll
            for (int mt = 0; mt < 2; mt++)
                #pragma unroll
                for (int np = 0; np < 8; np++)
                    #pragma unroll
                    for (int hh = 0; hh < 2; hh++) {
                        int r = rbase + mt*16 + (lane >> 2) + hh*8;
                        int cc = np*8 + (lane & 3)*2;
                        stg[r*68 + cc]     = acc[mt][np][hh*2+0];
                        stg[r*68 + cc + 1] = acc[mt][np][hh*2+1];
                    }
        }
        __syncthreads();
        {
            int r = tid >> 1, half = tid & 1;
            float bi = bias[r];
            float* dp = dst + ((size_t)b*256 + r)*TLEN + t0 + p2*64 + half*32;
            const float* st = stg + r*68 + half*32;
            #pragma unroll
            for (int j = 0; j < 8; j++) {
                float4 v = *(const float4*)(st + j*4);
                v.x += bi; v.y += bi; v.z += bi; v.w += bi;
                *(float4*)(dp + j*4) = v;
            }
        }
        __syncthreads();
    }
}

// ---------------- launch ----------------
extern "C" void kernel_launch(void* const* d_in, const int* in_sizes, int n_in,
                              void* d_out, int out_size) {
    const float* wav    = (const float*)d_in[0];
    const float* cond   = (const float*)d_in[1];
    const float* wav_w  = (const float*)d_in[2];
    const float* wav_b  = (const float*)d_in[3];
    const float* cond_w = (const float*)d_in[4];
    const float* cond_b = (const float*)d_in[5];
    const float* dil_w  = (const float*)d_in[6];
    const float* dil_b  = (const float*)d_in[7];
    const float* skip_w = (const float*)d_in[8];
    const float* skip_b = (const float*)d_in[9];
    const float* res_w  = (const float*)d_in[10];
    const float* res_b  = (const float*)d_in[11];
    const float* out_w  = (const float*)d_in[12];
    const float* out_b  = (const float*)d_in[13];
    const float* end_w  = (const float*)d_in[14];
    const float* end_b  = (const float*)d_in[15];

    cudaFuncSetAttribute(block_mma, cudaFuncAttributeMaxDynamicSharedMemorySize, SMEM_BLK);
    cudaFuncSetAttribute(final_mma, cudaFuncAttributeMaxDynamicSharedMemorySize, SMEM_FIN);

    pack_s1<<<(int)(((size_t)NBLK*11*2*256*40 + 255)/256), 256>>>(dil_w, cond_w);
    pack_s2<<<(int)(((size_t)NBLK*4*2*384*40 + 255)/256), 256>>>(skip_w, res_w);
    pack_f<<<(int)(((size_t)2*8*2*256*40 + 255)/256), 256>>>(out_w, end_w);
    pack_bias<<<(NBLK*640 + 255)/256, 256>>>(dil_b, cond_b, skip_b, res_b);
    init_resA<<<(int)(((size_t)BATCH*128*TLEN + 255)/256), 256>>>(wav, wav_w, wav_b);
    init_cnd<<<(int)(((size_t)BATCH*96*TLEN + 255)/256), 256>>>(cond);

    dim3 grid(TLEN / TN, BATCH);
    for (int i = 0; i < NBLK; i++) {
        int dnext = 1 << ((i + 1) % 8);
        block_mma<<<grid, 512, SMEM_BLK>>>(i, dnext, i & 1, (i == 0) ? 1 : 0, (i == NBLK-1) ? 1 : 0);
    }
    final_mma<<<grid, 512, SMEM_FIN>>>(0, out_b, nullptr);
    final_mma<<<grid, 512, SMEM_FIN>>>(1, end_b, (float*)d_out);
}